// round 17
// baseline (speedup 1.0000x reference)
#include <cuda_runtime.h>
#include <stdint.h>

#define IN_F   4096
#define OUT_F  4096
#define RANK   8
#define MAX_TOKENS 8192

#define ROWS      16                      // tokens per block
#define CHUNK     512                     // floats per row per chunk
#define NCHUNKS   (IN_F / CHUNK)          // 8
#define CHUNK_BYTES (ROWS * CHUNK * 4)    // 32 KB per buffer fill
#define SMEM_BYTES  (2 * ROWS * CHUNK * 4 + 16)   // 2 buffers + 2 mbarriers

// Intermediate t[tok][r] = x @ core1^T  (256 KB, lives in L2)
__device__ float g_t[MAX_TOKENS * RANK];

// ---- mbarrier / bulk-async helpers -----------------------------------------
__device__ __forceinline__ uint32_t smem_u32(const void* p) {
    uint32_t a;
    asm("{ .reg .u64 t; cvta.to.shared.u64 t, %1; cvt.u32.u64 %0, t; }"
        : "=r"(a) : "l"(p));
    return a;
}
#define MBARRIER_INIT(addr, count) \
    asm volatile("mbarrier.init.shared.b64 [%0], %1;" :: "r"(addr), "r"(count) : "memory")
#define MBARRIER_EXPECT_TX(addr, bytes) \
    asm volatile("mbarrier.arrive.expect_tx.shared.b64 _, [%0], %1;" :: "r"(addr), "r"(bytes) : "memory")
#define MBARRIER_WAIT_PARITY(addr, parity) do {                                   \
    uint32_t _mb = (addr), _ph = (parity), _done;                                 \
    asm volatile("{\n\t.reg .pred p;\n\t"                                         \
        "mbarrier.try_wait.parity.acquire.cta.shared::cta.b64 p, [%1], %2;\n\t"   \
        "selp.b32 %0, 1, 0, p;\n\t}"                                              \
        : "=r"(_done) : "r"(_mb), "r"(_ph) : "memory");                           \
    if (!_done) {                                                                 \
        asm volatile("{\n\t.reg .pred P1;\n\t"                                    \
            "WL_%=:\n\t"                                                          \
            "mbarrier.try_wait.parity.acquire.cta.shared::cta.b64 P1, [%0], %1, 0x989680;\n\t" \
            "@P1 bra.uni WD_%=;\n\t"                                              \
            "bra.uni WL_%=;\n\t"                                                  \
            "WD_%=:\n\t}" :: "r"(_mb), "r"(_ph) : "memory");                      \
    }                                                                             \
} while (0)

__device__ __forceinline__ void bulk_g2s(uint32_t dst, const void* src,
                                         uint32_t bytes, uint32_t mbar) {
    asm volatile(
        "cp.async.bulk.shared::cta.global.mbarrier::complete_tx::bytes "
        "[%0], [%1], %2, [%3];"
        :: "r"(dst), "l"(src), "r"(bytes), "r"(mbar) : "memory");
}

// ---------------------------------------------------------------------------
// Stage 1: t[tok, r] = sum_i x[tok, i] * core1[r, i]
// x streamed via cp.async.bulk (TMA path -> no LDG MSHR pressure): 16 rows x
// 2KB per chunk into a 2 x 32KB double buffer, mbarrier expect_tx pipeline.
// Compute = proven r6 scalar FFMA; warp w owns tokens 2w,2w+1; c1 via __ldg.
// 3 blocks/SM x 32KB prefetch = 96KB read-bytes in flight per SM.
// ---------------------------------------------------------------------------
__global__ void __launch_bounds__(256) tt_stage1(const float* __restrict__ x,
                                                 const float* __restrict__ c1) {
    extern __shared__ float xs[];                 // [2][ROWS][CHUNK]
    uint64_t* mbar64 = reinterpret_cast<uint64_t*>(xs + 2 * ROWS * CHUNK);

    const int tid  = threadIdx.x;
    const int warp = tid >> 5;
    const int lane = tid & 31;
    const int token0 = blockIdx.x * ROWS;

    const uint32_t mb0 = smem_u32(&mbar64[0]);
    const uint32_t mb1 = smem_u32(&mbar64[1]);

    if (tid == 0) {
        MBARRIER_INIT(mb0, 1);
        MBARRIER_INIT(mb1, 1);
    }
    __syncthreads();

    const char* xg = reinterpret_cast<const char*>(x) + (size_t)token0 * IN_F * 4;

    // Prologue: fill both buffers (chunks 0 and 1)
    if (tid == 0) {
#pragma unroll
        for (int b = 0; b < 2; b++) {
            const uint32_t mb = b ? mb1 : mb0;
            MBARRIER_EXPECT_TX(mb, CHUNK_BYTES);
            const uint32_t dst0 = smem_u32(xs + b * ROWS * CHUNK);
#pragma unroll
            for (int j = 0; j < ROWS; j++)
                bulk_g2s(dst0 + j * CHUNK * 4,
                         xg + (size_t)j * IN_F * 4 + b * CHUNK * 4,
                         CHUNK * 4, mb);
        }
    }

    float acc0[RANK], acc1[RANK];
#pragma unroll
    for (int r = 0; r < RANK; r++) { acc0[r] = 0.f; acc1[r] = 0.f; }

    const float4* cp = reinterpret_cast<const float4*>(c1);
    int ph0 = 0, ph1 = 0;

    for (int c = 0; c < NCHUNKS; c++) {
        const int b = c & 1;
        if (b == 0) { MBARRIER_WAIT_PARITY(mb0, ph0); ph0 ^= 1; }
        else        { MBARRIER_WAIT_PARITY(mb1, ph1); ph1 ^= 1; }

        const float4* r0p = reinterpret_cast<const float4*>(
            xs + b * ROWS * CHUNK + (warp * 2) * CHUNK);
        const float4* r1p = reinterpret_cast<const float4*>(
            xs + b * ROWS * CHUNK + (warp * 2 + 1) * CHUNK);

#pragma unroll
        for (int i = 0; i < CHUNK / 4 / 32; i++) {            // 4 iters
            const float4 x0 = r0p[lane + 32 * i];             // LDS.128
            const float4 x1 = r1p[lane + 32 * i];
            const int ci = c * (CHUNK / 4) + lane + 32 * i;
#pragma unroll
            for (int r = 0; r < RANK; r++) {
                const float4 cv = __ldg(cp + (size_t)r * (IN_F / 4) + ci);
                acc0[r] += x0.x * cv.x + x0.y * cv.y + x0.z * cv.z + x0.w * cv.w;
                acc1[r] += x1.x * cv.x + x1.y * cv.y + x1.z * cv.z + x1.w * cv.w;
            }
        }

        __syncthreads();                       // buffer fully consumed
        if (c + 2 < NCHUNKS && tid == 0) {     // refill this buffer
            const uint32_t mb = b ? mb1 : mb0;
            MBARRIER_EXPECT_TX(mb, CHUNK_BYTES);
            const uint32_t dst0 = smem_u32(xs + b * ROWS * CHUNK);
#pragma unroll
            for (int j = 0; j < ROWS; j++)
                bulk_g2s(dst0 + j * CHUNK * 4,
                         xg + (size_t)j * IN_F * 4 + (c + 2) * CHUNK * 4,
                         CHUNK * 4, mb);
        }
    }

    // Lane-reduce and store t for this warp's two tokens
#pragma unroll
    for (int r = 0; r < RANK; r++) {
        float v0 = acc0[r], v1 = acc1[r];
#pragma unroll
        for (int off = 16; off; off >>= 1) {
            v0 += __shfl_xor_sync(0xffffffffu, v0, off);
            v1 += __shfl_xor_sync(0xffffffffu, v1, off);
        }
        if (lane == 0) {
            g_t[(size_t)(token0 + warp * 2) * RANK + r]     = v0;
            g_t[(size_t)(token0 + warp * 2 + 1) * RANK + r] = v1;
        }
    }
}

// ---------------------------------------------------------------------------
// Stage 2: y[tok, o] = bias[o] + sum_r t[tok, r] * core0[o, r]
// Best-known body (25.6us): 64 tokens x 1024 outputs per block, t via
// LDS.128 float4 pairs, c0 coeffs in regs, STG.128 evict-first stores.
// ---------------------------------------------------------------------------
__global__ void __launch_bounds__(256) tt_stage2(const float* __restrict__ c0,
                                                 const float* __restrict__ bias,
                                                 float* __restrict__ y) {
    __shared__ float4 ts[64 * 2];
    const int tid = threadIdx.x;
    const int token0 = blockIdx.y * 64;
    const int o = blockIdx.x * 1024 + tid * 4;

    if (tid < 128) {
        const float4* tg = reinterpret_cast<const float4*>(g_t + (size_t)token0 * RANK);
        ts[tid] = tg[tid];
    }

    float4 ca[4], cb[4];
#pragma unroll
    for (int j = 0; j < 4; j++) {
        const float4* c = reinterpret_cast<const float4*>(c0 + (size_t)(o + j) * RANK);
        ca[j] = __ldg(c);
        cb[j] = __ldg(c + 1);
    }
    const float4 bv = __ldg(reinterpret_cast<const float4*>(bias + o));

    __syncthreads();

#pragma unroll 4
    for (int tok = 0; tok < 64; tok++) {
        const float4 tA = ts[tok * 2];
        const float4 tB = ts[tok * 2 + 1];

        float4 res;
        res.x = bv.x + ca[0].x * tA.x + ca[0].y * tA.y + ca[0].z * tA.z + ca[0].w * tA.w
                     + cb[0].x * tB.x + cb[0].y * tB.y + cb[0].z * tB.z + cb[0].w * tB.w;
        res.y = bv.y + ca[1].x * tA.x + ca[1].y * tA.y + ca[1].z * tA.z + ca[1].w * tA.w
                     + cb[1].x * tB.x + cb[1].y * tB.y + cb[1].z * tB.z + cb[1].w * tB.w;
        res.z = bv.z + ca[2].x * tA.x + ca[2].y * tA.y + ca[2].z * tA.z + ca[2].w * tA.w
                     + cb[2].x * tB.x + cb[2].y * tB.y + cb[2].z * tB.z + cb[2].w * tB.w;
        res.w = bv.w + ca[3].x * tA.x + ca[3].y * tA.y + ca[3].z * tA.z + ca[3].w * tA.w
                     + cb[3].x * tB.x + cb[3].y * tB.y + cb[3].z * tB.z + cb[3].w * tB.w;

        __stcs(reinterpret_cast<float4*>(y + (size_t)(token0 + tok) * OUT_F + o),
               res);
    }
}

extern "C" void kernel_launch(void* const* d_in, const int* in_sizes, int n_in,
                              void* d_out, int out_size) {
    const float* x    = (const float*)d_in[0];   // [TOKENS, IN_F]
    const float* c0   = (const float*)d_in[1];   // [OUT_F, RANK]
    const float* c1   = (const float*)d_in[2];   // [RANK, IN_F]
    const float* bias = (const float*)d_in[3];   // [OUT_F]
    float* y = (float*)d_out;

    const int tokens = in_sizes[0] / IN_F;       // 8192

    static bool once = []() {
        cudaFuncSetAttribute(tt_stage1,
                             cudaFuncAttributeMaxDynamicSharedMemorySize,
                             SMEM_BYTES);
        return true;
    }();
    (void)once;

    // Stage 1: 16 tokens/block, bulk-async double-buffered x stream
    tt_stage1<<<tokens / ROWS, 256, SMEM_BYTES>>>(x, c1);

    // Stage 2: 4 output chunks x 64-token groups = 512 blocks
    dim3 g2(OUT_F / 1024, tokens / 64);
    tt_stage2<<<g2, 256>>>(c0, bias, y);
}